// round 14
// baseline (speedup 1.0000x reference)
#include <cuda_runtime.h>
#include <cuda_bf16.h>
#include <cstdint>

// ---------------- Problem constants (fixed shapes) ----------------
#define N_  100000
#define E_  1200000
#define IN_ 128
#define H_  64
#define OUT_ 2
#define EPS_ 1e-5f

// ---------------- Device scratch (no allocations allowed) ----------------
__device__ int    g_deg[N_];
__device__ float  g_dinv[N_];
__device__ int    g_off[N_ + 1];
__device__ int    g_part[128];
__device__ int    g_cursor[N_];
__device__ float2 g_edge[E_];                 // {src as int bits, norm}
__device__ float  g_bufA[(size_t)N_ * H_];    // GEMM output (t)
__device__ float  g_bufB[(size_t)N_ * H_];    // aggregated h
__device__ float  g_A[3 * H_];                // BN scale per layer/feature
__device__ float  g_Bc[3 * H_];               // BN shift (incl. bias)

// ---------------- Fused zero(deg) + BN-affine prep ----------------
__global__ void zero_bn_k(const float* __restrict__ biases, const float* __restrict__ gamma,
                          const float* __restrict__ beta, const float* __restrict__ mean,
                          const float* __restrict__ var) {
    int i = blockIdx.x * blockDim.x + threadIdx.x;
    if (i < N_) g_deg[i] = 0;
    if (i < 3 * H_) {
        float s = gamma[i] * rsqrtf(var[i] + EPS_);
        g_A[i]  = s;
        g_Bc[i] = (biases[i] - mean[i]) * s + beta[i];
    }
}

__global__ void deg_k(const int* __restrict__ ei) {
    int e = blockIdx.x * blockDim.x + threadIdx.x;
    if (e >= E_) return;
    int d = ei[E_ + e];                // col (target), int32 on the wire
    if ((unsigned)d < (unsigned)N_) atomicAdd(&g_deg[d], 1);
}

// ---------------- Scan pass 1: per-1024 block sums + local exclusive ----------------
__global__ void scan1_k() {
    __shared__ int wsum[8];
    __shared__ int wpre[8];
    int tid  = threadIdx.x;
    int base = blockIdx.x * 1024 + tid * 4;
    int v[4]; int s = 0;
#pragma unroll
    for (int j = 0; j < 4; j++) {
        int i = base + j;
        v[j] = (i < N_) ? g_deg[i] : 0;
        if (i < N_) g_dinv[i] = rsqrtf((float)(v[j] + 1));   // +1 self loop
        s += v[j];
    }
    int lane = tid & 31, w = tid >> 5;
    int inc = s;
#pragma unroll
    for (int o = 1; o < 32; o <<= 1) {
        int t = __shfl_up_sync(0xffffffffu, inc, o);
        if (lane >= o) inc += t;
    }
    if (lane == 31) wsum[w] = inc;
    __syncthreads();
    if (tid == 0) {
        int r = 0;
#pragma unroll
        for (int k = 0; k < 8; k++) { wpre[k] = r; r += wsum[k]; }
        g_part[blockIdx.x] = r;          // raw block sum (not scanned)
    }
    __syncthreads();
    int ex = wpre[w] + (inc - s);
#pragma unroll
    for (int j = 0; j < 4; j++) {
        int i = base + j;
        if (i < N_) g_off[i] = ex;
        ex += v[j];
    }
}

// ---------------- Scan pass 2 (fused): each 256-node block reduces its one prefix ----------------
// Block b covers nodes [b*256, b*256+255]; all share partial index pidx = (b*256)>>10.
__global__ void scan3_k() {
    __shared__ int red[256];
    int tid = threadIdx.x;
    int pidx = (blockIdx.x << 8) >> 10;          // = blockIdx.x >> 2, block-constant
    int contrib = (tid < pidx) ? g_part[tid] : 0; // pidx <= 97 < 256
    red[tid] = contrib;
    __syncthreads();
#pragma unroll
    for (int o = 128; o >= 1; o >>= 1) {
        if (tid < o) red[tid] += red[tid + o];
        __syncthreads();
    }
    int pre = red[0];
    int i = blockIdx.x * blockDim.x + tid;
    if (i < N_) {
        int o = g_off[i] + pre;
        g_off[i]    = o;
        g_cursor[i] = o;
    }
    if (i == 0) g_off[N_] = E_;
}

// ---------------- CSR placement (counting sort by dst) ----------------
__global__ void place_k(const int* __restrict__ ei) {
    int e = blockIdx.x * blockDim.x + threadIdx.x;
    if (e >= E_) return;
    int s = ei[e];
    int d = ei[E_ + e];
    if ((unsigned)s >= (unsigned)N_ || (unsigned)d >= (unsigned)N_) return;
    float nm = g_dinv[s] * g_dinv[d];
    int p = atomicAdd(&g_cursor[d], 1);
    g_edge[p] = make_float2(__int_as_float(s), nm);
}

// ---------------- GEMM: [n,K] @ [K,64] -> g_bufA (4-k-step, float4 a-loads) ----------------
// Block tile: 64 nodes x 64 cols; thread tile: 4 nodes x 4 cols.
// Xs pad 68 (272 B rows, 16B-aligned) so a-loads are LDS.128 over 4 consecutive k.
template <int K, bool BN, bool EXT>
__global__ void __launch_bounds__(256) gemm_k(const float* __restrict__ Xext,
                                              const float* __restrict__ W,
                                              int abOff, int n) {
    __shared__ float Xs[64 * 68];
    __shared__ float Ws[64 * 64];
    const float* __restrict__ X = EXT ? Xext : g_bufB;
    int tid = threadIdx.x;
    int tx = tid & 15;      // 4-col group
    int ty = tid >> 4;      // 4-node group
    int node0 = blockIdx.x * 64;
    float acc[4][4] = {};

    for (int kc = 0; kc < K; kc += 64) {
        // stage W chunk [64 k x 64 cols]
#pragma unroll
        for (int m = 0; m < 16; m++) {
            int idx = tid + m * 256;
            int k = idx >> 6, j = idx & 63;
            Ws[idx] = W[(size_t)(kc + k) * 64 + j];
        }
        // stage X chunk [64 nodes x 64 k], node-major pad 68, fused BN+ReLU
#pragma unroll
        for (int m = 0; m < 16; m++) {
            int idx = tid + m * 256;
            int r = idx >> 6, c = idx & 63;
            int node = node0 + r;
            float v = (node < n) ? X[(size_t)node * K + kc + c] : 0.f;
            if (BN) v = fmaxf(fmaf(v, g_A[abOff + kc + c], g_Bc[abOff + kc + c]), 0.f);
            Xs[r * 68 + c] = v;
        }
        __syncthreads();
#pragma unroll
        for (int k = 0; k < 64; k += 4) {
            // one LDS.128 per node covering 4 k-steps
            float a_[4][4];
#pragma unroll
            for (int i = 0; i < 4; i++)
                *(float4*)a_[i] = *(const float4*)&Xs[(ty * 4 + i) * 68 + k];
#pragma unroll
            for (int j = 0; j < 4; j++) {
                float4 b = *(const float4*)&Ws[(k + j) * 64 + tx * 4];
#pragma unroll
                for (int i = 0; i < 4; i++) {
                    float a = a_[i][j];
                    acc[i][0] = fmaf(a, b.x, acc[i][0]);
                    acc[i][1] = fmaf(a, b.y, acc[i][1]);
                    acc[i][2] = fmaf(a, b.z, acc[i][2]);
                    acc[i][3] = fmaf(a, b.w, acc[i][3]);
                }
            }
        }
        __syncthreads();
    }
#pragma unroll
    for (int i = 0; i < 4; i++) {
        int node = node0 + ty * 4 + i;
        if (node < n)
            *(float4*)&g_bufA[(size_t)node * 64 + tx * 4] =
                make_float4(acc[i][0], acc[i][1], acc[i][2], acc[i][3]);
    }
}

// ---------------- Pull aggregation (proven): one-ahead prefetch ----------------
__global__ void __launch_bounds__(256) gather_k(int n) {
    int hw = (blockIdx.x * blockDim.x + threadIdx.x) >> 4;  // half-warp per node
    int l  = threadIdx.x & 15;                               // float4 slice of the row
    if (hw >= n) return;
    int node = hw;
    float d = g_dinv[node];
    float4 acc = *(const float4*)&g_bufA[(size_t)node * 64 + l * 4];
    float d2 = d * d;
    acc.x *= d2; acc.y *= d2; acc.z *= d2; acc.w *= d2;

    int s = g_off[node], e = g_off[node + 1];
    float2 ed;
    if (s < e) ed = __ldg(&g_edge[s]);
    for (int i = s; i < e; i++) {
        int src  = __float_as_int(ed.x);
        float w  = ed.y;
        if (i + 1 < e) ed = __ldg(&g_edge[i + 1]);   // prefetch next edge record
        float4 v = *(const float4*)&g_bufA[(size_t)src * 64 + l * 4];
        acc.x = fmaf(w, v.x, acc.x);
        acc.y = fmaf(w, v.y, acc.y);
        acc.z = fmaf(w, v.z, acc.z);
        acc.w = fmaf(w, v.w, acc.w);
    }
    *(float4*)&g_bufB[(size_t)node * 64 + l * 4] = acc;
}

// ---------------- Fused gather3 + BN2 + ReLU + classifier ----------------
__global__ void __launch_bounds__(256) gather_cls_k(const float* __restrict__ cw,
                                                    const float* __restrict__ cb,
                                                    float* __restrict__ out, int n) {
    int hw = (blockIdx.x * blockDim.x + threadIdx.x) >> 4;  // half-warp per node
    int l  = threadIdx.x & 15;                               // float4 slice of the row
    if (hw >= n) return;
    int node = hw;
    float d = g_dinv[node];
    float4 acc = *(const float4*)&g_bufA[(size_t)node * 64 + l * 4];
    float d2 = d * d;
    acc.x *= d2; acc.y *= d2; acc.z *= d2; acc.w *= d2;

    int s = g_off[node], e = g_off[node + 1];
    float2 ed;
    if (s < e) ed = __ldg(&g_edge[s]);
    for (int i = s; i < e; i++) {
        int src  = __float_as_int(ed.x);
        float w  = ed.y;
        if (i + 1 < e) ed = __ldg(&g_edge[i + 1]);
        float4 v = *(const float4*)&g_bufA[(size_t)src * 64 + l * 4];
        acc.x = fmaf(w, v.x, acc.x);
        acc.y = fmaf(w, v.y, acc.y);
        acc.z = fmaf(w, v.z, acc.z);
        acc.w = fmaf(w, v.w, acc.w);
    }

    // BN2 + ReLU + partial classifier for features c = l*4 .. l*4+3
    int c0 = l * 4;
    float a0 = 0.f, a1 = 0.f;
    float hv[4] = {acc.x, acc.y, acc.z, acc.w};
#pragma unroll
    for (int j = 0; j < 4; j++) {
        int c = c0 + j;
        float h = fmaxf(fmaf(hv[j], g_A[128 + c], g_Bc[128 + c]), 0.f);
        a0 = fmaf(h, __ldg(&cw[c * 2 + 0]), a0);
        a1 = fmaf(h, __ldg(&cw[c * 2 + 1]), a1);
    }
    // reduce across the 16 lanes of the half-warp (xor butterfly stays in-group)
#pragma unroll
    for (int o = 8; o >= 1; o >>= 1) {
        a0 += __shfl_xor_sync(0xffffffffu, a0, o);
        a1 += __shfl_xor_sync(0xffffffffu, a1, o);
    }
    if (l == 0) {
        out[(size_t)node * 2 + 0] = a0 + __ldg(&cb[0]);
        out[(size_t)node * 2 + 1] = a1 + __ldg(&cb[1]);
    }
}

// ---------------- Launch ----------------
extern "C" void kernel_launch(void* const* d_in, const int* in_sizes, int n_in,
                              void* d_out, int out_size) {
    const float* x      = (const float*)d_in[0];
    const int*   ei     = (const int*)d_in[1];     // int32 on the wire
    const float* w0     = (const float*)d_in[2];
    const float* w1     = (const float*)d_in[3];
    const float* w2     = (const float*)d_in[4];
    const float* biases = (const float*)d_in[5];
    const float* gamma  = (const float*)d_in[6];
    const float* beta   = (const float*)d_in[7];
    const float* rmean  = (const float*)d_in[8];
    const float* rvar   = (const float*)d_in[9];
    const float* clsw   = (const float*)d_in[10];
    const float* clsb   = (const float*)d_in[11];
    float* out = (float*)d_out;

    const int n = N_;
    const int nodeBlocks   = (n + 255) / 256;
    const int edgeBlocks   = (E_ + 255) / 256;
    const int scanBlocks   = (n + 1023) / 1024;      // 98
    const int gemmBlocks   = (n + 63) / 64;          // 1563
    const int gatherBlocks = (n * 16 + 255) / 256;   // half-warp per node

    // launch index 3 (the ncu-profiled slot) = gemm_k<128> — it only needs x,w0
    zero_bn_k<<<nodeBlocks, 256>>>(biases, gamma, beta, rmean, rvar);   // 0
    deg_k<<<edgeBlocks, 256>>>(ei);                                     // 1
    scan1_k<<<scanBlocks, 256>>>();                                     // 2 (+dinv)
    gemm_k<128, false, true><<<gemmBlocks, 256>>>(x, w0, 0, n);         // 3 <- profiled
    scan3_k<<<nodeBlocks, 256>>>();                                     // 4 (scan2 fused in)
    place_k<<<edgeBlocks, 256>>>(ei);                                   // 5

    // --- layer 0 aggregate ---
    gather_k<<<gatherBlocks, 256>>>(n);                                 // 6
    // --- layer 1 ---
    gemm_k<64, true, false><<<gemmBlocks, 256>>>(nullptr, w1, 0, n);    // 7
    gather_k<<<gatherBlocks, 256>>>(n);                                 // 8
    // --- layer 2 ---
    gemm_k<64, true, false><<<gemmBlocks, 256>>>(nullptr, w2, 64, n);   // 9
    gather_cls_k<<<gatherBlocks, 256>>>(clsw, clsb, out, n);            // 10 (fused)
}

// round 15
// speedup vs baseline: 1.1529x; 1.1529x over previous
#include <cuda_runtime.h>
#include <cuda_bf16.h>
#include <cstdint>

// ---------------- Problem constants (fixed shapes) ----------------
#define N_  100000
#define E_  1200000
#define IN_ 128
#define H_  64
#define OUT_ 2
#define EPS_ 1e-5f

// ---------------- Device scratch (no allocations allowed) ----------------
__device__ int    g_deg[N_];
__device__ float  g_dinv[N_];
__device__ int    g_off[N_ + 1];
__device__ int    g_part[128];
__device__ int    g_cursor[N_];
__device__ float2 g_edge[E_];                 // {src as int bits, norm}
__device__ float  g_bufA[(size_t)N_ * H_];    // GEMM output (t)
__device__ float  g_bufB[(size_t)N_ * H_];    // aggregated h
__device__ float  g_A[3 * H_];                // BN scale per layer/feature
__device__ float  g_Bc[3 * H_];               // BN shift (incl. bias)

// ---------------- tf32 helpers ----------------
__device__ __forceinline__ uint32_t tf32cvt(float f) {
    uint32_t u;
    asm("cvt.rna.tf32.f32 %0, %1;" : "=r"(u) : "f"(f));
    return u;
}
__device__ __forceinline__ void mma_tf32(float* c, uint32_t a0, uint32_t a1,
                                         uint32_t a2, uint32_t a3,
                                         uint32_t b0, uint32_t b1) {
    asm("mma.sync.aligned.m16n8k8.row.col.f32.tf32.tf32.f32 "
        "{%0,%1,%2,%3},{%4,%5,%6,%7},{%8,%9},{%0,%1,%2,%3};"
        : "+f"(c[0]), "+f"(c[1]), "+f"(c[2]), "+f"(c[3])
        : "r"(a0), "r"(a1), "r"(a2), "r"(a3), "r"(b0), "r"(b1));
}

// ---------------- Fused zero(deg) + BN-affine prep ----------------
__global__ void zero_bn_k(const float* __restrict__ biases, const float* __restrict__ gamma,
                          const float* __restrict__ beta, const float* __restrict__ mean,
                          const float* __restrict__ var) {
    int i = blockIdx.x * blockDim.x + threadIdx.x;
    if (i < N_) g_deg[i] = 0;
    if (i < 3 * H_) {
        float s = gamma[i] * rsqrtf(var[i] + EPS_);
        g_A[i]  = s;
        g_Bc[i] = (biases[i] - mean[i]) * s + beta[i];
    }
}

__global__ void deg_k(const int* __restrict__ ei) {
    int e = blockIdx.x * blockDim.x + threadIdx.x;
    if (e >= E_) return;
    int d = ei[E_ + e];                // col (target), int32 on the wire
    if ((unsigned)d < (unsigned)N_) atomicAdd(&g_deg[d], 1);
}

// ---------------- Exclusive scan over g_deg -> g_off (+dinv fused) ----------------
__global__ void scan1_k() {
    __shared__ int wsum[8];
    __shared__ int wpre[8];
    int tid  = threadIdx.x;
    int base = blockIdx.x * 1024 + tid * 4;
    int v[4]; int s = 0;
#pragma unroll
    for (int j = 0; j < 4; j++) {
        int i = base + j;
        v[j] = (i < N_) ? g_deg[i] : 0;
        if (i < N_) g_dinv[i] = rsqrtf((float)(v[j] + 1));   // +1 self loop
        s += v[j];
    }
    int lane = tid & 31, w = tid >> 5;
    int inc = s;
#pragma unroll
    for (int o = 1; o < 32; o <<= 1) {
        int t = __shfl_up_sync(0xffffffffu, inc, o);
        if (lane >= o) inc += t;
    }
    if (lane == 31) wsum[w] = inc;
    __syncthreads();
    if (tid == 0) {
        int r = 0;
#pragma unroll
        for (int k = 0; k < 8; k++) { wpre[k] = r; r += wsum[k]; }
        g_part[blockIdx.x] = r;
    }
    __syncthreads();
    int ex = wpre[w] + (inc - s);
#pragma unroll
    for (int j = 0; j < 4; j++) {
        int i = base + j;
        if (i < N_) g_off[i] = ex;
        ex += v[j];
    }
}

__global__ void scan2_k(int nb) {
    __shared__ int s[128];
    int t = threadIdx.x;
    int v = (t < nb) ? g_part[t] : 0;
    s[t] = v;
    __syncthreads();
#pragma unroll
    for (int o = 1; o < 128; o <<= 1) {
        int x = (t >= o) ? s[t - o] : 0;
        __syncthreads();
        s[t] += x;
        __syncthreads();
    }
    if (t < nb) g_part[t] = s[t] - v;   // exclusive
}

__global__ void scan3_k() {
    int i = blockIdx.x * blockDim.x + threadIdx.x;
    if (i < N_) {
        int o = g_off[i] + g_part[i >> 10];
        g_off[i]    = o;
        g_cursor[i] = o;
    }
    if (i == 0) g_off[N_] = E_;
}

// ---------------- CSR placement (counting sort by dst) ----------------
__global__ void place_k(const int* __restrict__ ei) {
    int e = blockIdx.x * blockDim.x + threadIdx.x;
    if (e >= E_) return;
    int s = ei[e];
    int d = ei[E_ + e];
    if ((unsigned)s >= (unsigned)N_ || (unsigned)d >= (unsigned)N_) return;
    float nm = g_dinv[s] * g_dinv[d];
    int p = atomicAdd(&g_cursor[d], 1);
    g_edge[p] = make_float2(__int_as_float(s), nm);
}

// ---------------- tf32 MMA GEMM: [n,K] @ [K,64] -> g_bufA ----------------
// Block: 128 nodes x 64 cols, 256 threads (8 warps). Warp: 16 rows x 8 n-tiles.
// m16n8k8 tf32 mma. Xs stride 36 / Ws stride 72 -> conflict-free fragment LDS.
#define KC_   32
#define XSTR_ 36
#define WSTR_ 72
template <int K, bool BN, bool EXT>
__global__ void __launch_bounds__(256) gemmt_k(const float* __restrict__ Xext,
                                               const float* __restrict__ W,
                                               int abOff, int n) {
    __shared__ uint32_t Xs[128 * XSTR_];   // 18.4 KB
    __shared__ uint32_t Ws[KC_ * WSTR_];   //  9.2 KB
    const float* __restrict__ X = EXT ? Xext : g_bufB;
    int tid  = threadIdx.x;
    int lane = tid & 31, wid = tid >> 5;
    int gid  = lane >> 2, tgid = lane & 3;
    int node0 = blockIdx.x * 128;
    int wn0   = wid * 16;

    float acc[8][4];
#pragma unroll
    for (int t = 0; t < 8; t++)
#pragma unroll
        for (int j = 0; j < 4; j++) acc[t][j] = 0.f;

    for (int kc = 0; kc < K; kc += KC_) {
        // stage W chunk [32 k x 64 n] (tf32-converted)
#pragma unroll
        for (int m = 0; m < 8; m++) {
            int idx = tid + m * 256;
            int k = idx >> 6, j = idx & 63;
            Ws[k * WSTR_ + j] = tf32cvt(W[(size_t)(kc + k) * 64 + j]);
        }
        // stage X chunk [128 nodes x 32 k], fused BN+ReLU, tf32-converted
#pragma unroll
        for (int m = 0; m < 16; m++) {
            int idx = tid + m * 256;
            int r = idx >> 5, c = idx & 31;
            int node = node0 + r;
            float v = (node < n) ? X[(size_t)node * K + kc + c] : 0.f;
            if (BN) v = fmaxf(fmaf(v, g_A[abOff + kc + c], g_Bc[abOff + kc + c]), 0.f);
            Xs[r * XSTR_ + c] = tf32cvt(v);
        }
        __syncthreads();
#pragma unroll
        for (int k8 = 0; k8 < KC_; k8 += 8) {
            int r0 = wn0 + gid;
            uint32_t a0 = Xs[r0 * XSTR_ + k8 + tgid];
            uint32_t a1 = Xs[(r0 + 8) * XSTR_ + k8 + tgid];
            uint32_t a2 = Xs[r0 * XSTR_ + k8 + tgid + 4];
            uint32_t a3 = Xs[(r0 + 8) * XSTR_ + k8 + tgid + 4];
#pragma unroll
            for (int nt = 0; nt < 8; nt++) {
                uint32_t b0 = Ws[(k8 + tgid) * WSTR_ + nt * 8 + gid];
                uint32_t b1 = Ws[(k8 + tgid + 4) * WSTR_ + nt * 8 + gid];
                mma_tf32(acc[nt], a0, a1, a2, a3, b0, b1);
            }
        }
        __syncthreads();
    }
    // store: per n-tile, rows (wn0+gid) and (wn0+gid+8), cols nt*8 + tgid*2 .. +1
    int nodeA = node0 + wn0 + gid;
    int nodeB = nodeA + 8;
#pragma unroll
    for (int nt = 0; nt < 8; nt++) {
        int col = nt * 8 + tgid * 2;
        if (nodeA < n)
            *(float2*)&g_bufA[(size_t)nodeA * 64 + col] = make_float2(acc[nt][0], acc[nt][1]);
        if (nodeB < n)
            *(float2*)&g_bufA[(size_t)nodeB * 64 + col] = make_float2(acc[nt][2], acc[nt][3]);
    }
}

// ---------------- Pull aggregation (proven): one-ahead prefetch ----------------
__global__ void __launch_bounds__(256) gather_k(int n) {
    int hw = (blockIdx.x * blockDim.x + threadIdx.x) >> 4;  // half-warp per node
    int l  = threadIdx.x & 15;                               // float4 slice of the row
    if (hw >= n) return;
    int node = hw;
    float d = g_dinv[node];
    float4 acc = *(const float4*)&g_bufA[(size_t)node * 64 + l * 4];
    float d2 = d * d;
    acc.x *= d2; acc.y *= d2; acc.z *= d2; acc.w *= d2;

    int s = g_off[node], e = g_off[node + 1];
    float2 ed;
    if (s < e) ed = __ldg(&g_edge[s]);
    for (int i = s; i < e; i++) {
        int src  = __float_as_int(ed.x);
        float w  = ed.y;
        if (i + 1 < e) ed = __ldg(&g_edge[i + 1]);   // prefetch next edge record
        float4 v = *(const float4*)&g_bufA[(size_t)src * 64 + l * 4];
        acc.x = fmaf(w, v.x, acc.x);
        acc.y = fmaf(w, v.y, acc.y);
        acc.z = fmaf(w, v.z, acc.z);
        acc.w = fmaf(w, v.w, acc.w);
    }
    *(float4*)&g_bufB[(size_t)node * 64 + l * 4] = acc;
}

// ---------------- Fused gather3 + BN2 + ReLU + classifier ----------------
__global__ void __launch_bounds__(256) gather_cls_k(const float* __restrict__ cw,
                                                    const float* __restrict__ cb,
                                                    float* __restrict__ out, int n) {
    int hw = (blockIdx.x * blockDim.x + threadIdx.x) >> 4;  // half-warp per node
    int l  = threadIdx.x & 15;                               // float4 slice of the row
    if (hw >= n) return;
    int node = hw;
    float d = g_dinv[node];
    float4 acc = *(const float4*)&g_bufA[(size_t)node * 64 + l * 4];
    float d2 = d * d;
    acc.x *= d2; acc.y *= d2; acc.z *= d2; acc.w *= d2;

    int s = g_off[node], e = g_off[node + 1];
    float2 ed;
    if (s < e) ed = __ldg(&g_edge[s]);
    for (int i = s; i < e; i++) {
        int src  = __float_as_int(ed.x);
        float w  = ed.y;
        if (i + 1 < e) ed = __ldg(&g_edge[i + 1]);
        float4 v = *(const float4*)&g_bufA[(size_t)src * 64 + l * 4];
        acc.x = fmaf(w, v.x, acc.x);
        acc.y = fmaf(w, v.y, acc.y);
        acc.z = fmaf(w, v.z, acc.z);
        acc.w = fmaf(w, v.w, acc.w);
    }

    // BN2 + ReLU + partial classifier for features c = l*4 .. l*4+3
    int c0 = l * 4;
    float a0 = 0.f, a1 = 0.f;
    float hv[4] = {acc.x, acc.y, acc.z, acc.w};
#pragma unroll
    for (int j = 0; j < 4; j++) {
        int c = c0 + j;
        float h = fmaxf(fmaf(hv[j], g_A[128 + c], g_Bc[128 + c]), 0.f);
        a0 = fmaf(h, __ldg(&cw[c * 2 + 0]), a0);
        a1 = fmaf(h, __ldg(&cw[c * 2 + 1]), a1);
    }
    // reduce across the 16 lanes of the half-warp (xor butterfly stays in-group)
#pragma unroll
    for (int o = 8; o >= 1; o >>= 1) {
        a0 += __shfl_xor_sync(0xffffffffu, a0, o);
        a1 += __shfl_xor_sync(0xffffffffu, a1, o);
    }
    if (l == 0) {
        out[(size_t)node * 2 + 0] = a0 + __ldg(&cb[0]);
        out[(size_t)node * 2 + 1] = a1 + __ldg(&cb[1]);
    }
}

// ---------------- Launch ----------------
extern "C" void kernel_launch(void* const* d_in, const int* in_sizes, int n_in,
                              void* d_out, int out_size) {
    const float* x      = (const float*)d_in[0];
    const int*   ei     = (const int*)d_in[1];     // int32 on the wire
    const float* w0     = (const float*)d_in[2];
    const float* w1     = (const float*)d_in[3];
    const float* w2     = (const float*)d_in[4];
    const float* biases = (const float*)d_in[5];
    const float* gamma  = (const float*)d_in[6];
    const float* beta   = (const float*)d_in[7];
    const float* rmean  = (const float*)d_in[8];
    const float* rvar   = (const float*)d_in[9];
    const float* clsw   = (const float*)d_in[10];
    const float* clsb   = (const float*)d_in[11];
    float* out = (float*)d_out;

    const int n = N_;
    const int nodeBlocks   = (n + 255) / 256;
    const int edgeBlocks   = (E_ + 255) / 256;
    const int scanBlocks   = (n + 1023) / 1024;      // 98
    const int gemmBlocks   = (n + 127) / 128;        // 782
    const int gatherBlocks = (n * 16 + 255) / 256;   // half-warp per node

    // launch index 3 (the ncu-profiled slot) = gemmt_k<128> — it only needs x,w0
    zero_bn_k<<<nodeBlocks, 256>>>(biases, gamma, beta, rmean, rvar);   // 0
    deg_k<<<edgeBlocks, 256>>>(ei);                                     // 1
    scan1_k<<<scanBlocks, 256>>>();                                     // 2 (+dinv)
    gemmt_k<128, false, true><<<gemmBlocks, 256>>>(x, w0, 0, n);        // 3 <- profiled
    scan2_k<<<1, 128>>>(scanBlocks);                                    // 4
    scan3_k<<<nodeBlocks, 256>>>();                                     // 5
    place_k<<<edgeBlocks, 256>>>(ei);                                   // 6

    // --- layer 0 aggregate ---
    gather_k<<<gatherBlocks, 256>>>(n);                                 // 7
    // --- layer 1 ---
    gemmt_k<64, true, false><<<gemmBlocks, 256>>>(nullptr, w1, 0, n);   // 8
    gather_k<<<gatherBlocks, 256>>>(n);                                 // 9
    // --- layer 2 ---
    gemmt_k<64, true, false><<<gemmBlocks, 256>>>(nullptr, w2, 64, n);  // 10
    gather_cls_k<<<gatherBlocks, 256>>>(clsw, clsb, out, n);            // 11 (fused)
}

// round 16
// speedup vs baseline: 1.1787x; 1.0223x over previous
#include <cuda_runtime.h>
#include <cuda_bf16.h>
#include <cuda_fp16.h>
#include <cstdint>

// ---------------- Problem constants (fixed shapes) ----------------
#define N_  100000
#define E_  1200000
#define IN_ 128
#define H_  64
#define OUT_ 2
#define EPS_ 1e-5f

// ---------------- Device scratch (no allocations allowed) ----------------
__device__ int    g_deg[N_];
__device__ float  g_dinv[N_];
__device__ int    g_off[N_ + 1];
__device__ int    g_part[128];
__device__ int    g_cursor[N_];
__device__ float2 g_edge[E_];                  // {src as int bits, norm}
__device__ __half g_bufAh[(size_t)N_ * H_];    // GEMM output t (fp16 rows, 128 B)
__device__ float  g_bufB[(size_t)N_ * H_];     // aggregated h (fp32)
__device__ float  g_A[3 * H_];                 // BN scale per layer/feature
__device__ float  g_Bc[3 * H_];                // BN shift (incl. bias)

// ---------------- tf32 helpers ----------------
__device__ __forceinline__ uint32_t tf32cvt(float f) {
    uint32_t u;
    asm("cvt.rna.tf32.f32 %0, %1;" : "=r"(u) : "f"(f));
    return u;
}
__device__ __forceinline__ void mma_tf32(float* c, uint32_t a0, uint32_t a1,
                                         uint32_t a2, uint32_t a3,
                                         uint32_t b0, uint32_t b1) {
    asm("mma.sync.aligned.m16n8k8.row.col.f32.tf32.tf32.f32 "
        "{%0,%1,%2,%3},{%4,%5,%6,%7},{%8,%9},{%0,%1,%2,%3};"
        : "+f"(c[0]), "+f"(c[1]), "+f"(c[2]), "+f"(c[3])
        : "r"(a0), "r"(a1), "r"(a2), "r"(a3), "r"(b0), "r"(b1));
}

// ---------------- Fused zero(deg) + BN-affine prep ----------------
__global__ void zero_bn_k(const float* __restrict__ biases, const float* __restrict__ gamma,
                          const float* __restrict__ beta, const float* __restrict__ mean,
                          const float* __restrict__ var) {
    int i = blockIdx.x * blockDim.x + threadIdx.x;
    if (i < N_) g_deg[i] = 0;
    if (i < 3 * H_) {
        float s = gamma[i] * rsqrtf(var[i] + EPS_);
        g_A[i]  = s;
        g_Bc[i] = (biases[i] - mean[i]) * s + beta[i];
    }
}

__global__ void deg_k(const int* __restrict__ ei) {
    int e = blockIdx.x * blockDim.x + threadIdx.x;
    if (e >= E_) return;
    int d = ei[E_ + e];                // col (target), int32 on the wire
    if ((unsigned)d < (unsigned)N_) atomicAdd(&g_deg[d], 1);
}

// ---------------- Exclusive scan over g_deg -> g_off (+dinv fused) ----------------
__global__ void scan1_k() {
    __shared__ int wsum[8];
    __shared__ int wpre[8];
    int tid  = threadIdx.x;
    int base = blockIdx.x * 1024 + tid * 4;
    int v[4]; int s = 0;
#pragma unroll
    for (int j = 0; j < 4; j++) {
        int i = base + j;
        v[j] = (i < N_) ? g_deg[i] : 0;
        if (i < N_) g_dinv[i] = rsqrtf((float)(v[j] + 1));   // +1 self loop
        s += v[j];
    }
    int lane = tid & 31, w = tid >> 5;
    int inc = s;
#pragma unroll
    for (int o = 1; o < 32; o <<= 1) {
        int t = __shfl_up_sync(0xffffffffu, inc, o);
        if (lane >= o) inc += t;
    }
    if (lane == 31) wsum[w] = inc;
    __syncthreads();
    if (tid == 0) {
        int r = 0;
#pragma unroll
        for (int k = 0; k < 8; k++) { wpre[k] = r; r += wsum[k]; }
        g_part[blockIdx.x] = r;
    }
    __syncthreads();
    int ex = wpre[w] + (inc - s);
#pragma unroll
    for (int j = 0; j < 4; j++) {
        int i = base + j;
        if (i < N_) g_off[i] = ex;
        ex += v[j];
    }
}

__global__ void scan2_k(int nb) {
    __shared__ int s[128];
    int t = threadIdx.x;
    int v = (t < nb) ? g_part[t] : 0;
    s[t] = v;
    __syncthreads();
#pragma unroll
    for (int o = 1; o < 128; o <<= 1) {
        int x = (t >= o) ? s[t - o] : 0;
        __syncthreads();
        s[t] += x;
        __syncthreads();
    }
    if (t < nb) g_part[t] = s[t] - v;   // exclusive
}

__global__ void scan3_k() {
    int i = blockIdx.x * blockDim.x + threadIdx.x;
    if (i < N_) {
        int o = g_off[i] + g_part[i >> 10];
        g_off[i]    = o;
        g_cursor[i] = o;
    }
    if (i == 0) g_off[N_] = E_;
}

// ---------------- CSR placement (counting sort by dst) ----------------
__global__ void place_k(const int* __restrict__ ei) {
    int e = blockIdx.x * blockDim.x + threadIdx.x;
    if (e >= E_) return;
    int s = ei[e];
    int d = ei[E_ + e];
    if ((unsigned)s >= (unsigned)N_ || (unsigned)d >= (unsigned)N_) return;
    float nm = g_dinv[s] * g_dinv[d];
    int p = atomicAdd(&g_cursor[d], 1);
    g_edge[p] = make_float2(__int_as_float(s), nm);
}

// ---------------- tf32 MMA GEMM: [n,K] @ [K,64] -> g_bufAh (fp16) ----------------
// Block: 128 nodes x 64 cols, 256 threads (8 warps). Warp: 16 rows x 8 n-tiles.
#define KC_   32
#define XSTR_ 36
#define WSTR_ 72
template <int K, bool BN, bool EXT>
__global__ void __launch_bounds__(256) gemmt_k(const float* __restrict__ Xext,
                                               const float* __restrict__ W,
                                               int abOff, int n) {
    __shared__ uint32_t Xs[128 * XSTR_];   // 18.4 KB
    __shared__ uint32_t Ws[KC_ * WSTR_];   //  9.2 KB
    const float* __restrict__ X = EXT ? Xext : g_bufB;
    int tid  = threadIdx.x;
    int lane = tid & 31, wid = tid >> 5;
    int gid  = lane >> 2, tgid = lane & 3;
    int node0 = blockIdx.x * 128;
    int wn0   = wid * 16;

    float acc[8][4];
#pragma unroll
    for (int t = 0; t < 8; t++)
#pragma unroll
        for (int j = 0; j < 4; j++) acc[t][j] = 0.f;

    for (int kc = 0; kc < K; kc += KC_) {
        // stage W chunk [32 k x 64 n] (tf32-converted)
#pragma unroll
        for (int m = 0; m < 8; m++) {
            int idx = tid + m * 256;
            int k = idx >> 6, j = idx & 63;
            Ws[k * WSTR_ + j] = tf32cvt(W[(size_t)(kc + k) * 64 + j]);
        }
        // stage X chunk [128 nodes x 32 k], fused BN+ReLU, tf32-converted
#pragma unroll
        for (int m = 0; m < 16; m++) {
            int idx = tid + m * 256;
            int r = idx >> 5, c = idx & 31;
            int node = node0 + r;
            float v = (node < n) ? X[(size_t)node * K + kc + c] : 0.f;
            if (BN) v = fmaxf(fmaf(v, g_A[abOff + kc + c], g_Bc[abOff + kc + c]), 0.f);
            Xs[r * XSTR_ + c] = tf32cvt(v);
        }
        __syncthreads();
#pragma unroll
        for (int k8 = 0; k8 < KC_; k8 += 8) {
            int r0 = wn0 + gid;
            uint32_t a0 = Xs[r0 * XSTR_ + k8 + tgid];
            uint32_t a1 = Xs[(r0 + 8) * XSTR_ + k8 + tgid];
            uint32_t a2 = Xs[r0 * XSTR_ + k8 + tgid + 4];
            uint32_t a3 = Xs[(r0 + 8) * XSTR_ + k8 + tgid + 4];
#pragma unroll
            for (int nt = 0; nt < 8; nt++) {
                uint32_t b0 = Ws[(k8 + tgid) * WSTR_ + nt * 8 + gid];
                uint32_t b1 = Ws[(k8 + tgid + 4) * WSTR_ + nt * 8 + gid];
                mma_tf32(acc[nt], a0, a1, a2, a3, b0, b1);
            }
        }
        __syncthreads();
    }
    // store fp16: per n-tile, rows (wn0+gid) and (+8), cols nt*8 + tgid*2 .. +1
    int nodeA = node0 + wn0 + gid;
    int nodeB = nodeA + 8;
#pragma unroll
    for (int nt = 0; nt < 8; nt++) {
        int col = nt * 8 + tgid * 2;
        if (nodeA < n)
            *(__half2*)&g_bufAh[(size_t)nodeA * 64 + col] = __floats2half2_rn(acc[nt][0], acc[nt][1]);
        if (nodeB < n)
            *(__half2*)&g_bufAh[(size_t)nodeB * 64 + col] = __floats2half2_rn(acc[nt][2], acc[nt][3]);
    }
}

// ---------------- fp16 row slice load helper: 4 features (8 B) -> float4 ----------------
__device__ __forceinline__ float4 ldrow4h(const __half* p) {
    uint2 u = *(const uint2*)p;
    __half2 ha = *(__half2*)&u.x, hb = *(__half2*)&u.y;
    float2 fa = __half22float2(ha), fb = __half22float2(hb);
    return make_float4(fa.x, fa.y, fb.x, fb.y);
}

// ---------------- Pull aggregation: fp16 bufA reads, fp32 accumulate ----------------
__global__ void __launch_bounds__(256) gather_k(int n) {
    int hw = (blockIdx.x * blockDim.x + threadIdx.x) >> 4;  // half-warp per node
    int l  = threadIdx.x & 15;                               // 4-feature slice of the row
    if (hw >= n) return;
    int node = hw;
    float d = g_dinv[node];
    float4 acc = ldrow4h(&g_bufAh[(size_t)node * 64 + l * 4]);
    float d2 = d * d;
    acc.x *= d2; acc.y *= d2; acc.z *= d2; acc.w *= d2;

    int s = g_off[node], e = g_off[node + 1];
    float2 ed;
    if (s < e) ed = __ldg(&g_edge[s]);
    for (int i = s; i < e; i++) {
        int src  = __float_as_int(ed.x);
        float w  = ed.y;
        if (i + 1 < e) ed = __ldg(&g_edge[i + 1]);   // prefetch next edge record
        float4 v = ldrow4h(&g_bufAh[(size_t)src * 64 + l * 4]);
        acc.x = fmaf(w, v.x, acc.x);
        acc.y = fmaf(w, v.y, acc.y);
        acc.z = fmaf(w, v.z, acc.z);
        acc.w = fmaf(w, v.w, acc.w);
    }
    *(float4*)&g_bufB[(size_t)node * 64 + l * 4] = acc;
}

// ---------------- Fused gather3 + BN2 + ReLU + classifier ----------------
__global__ void __launch_bounds__(256) gather_cls_k(const float* __restrict__ cw,
                                                    const float* __restrict__ cb,
                                                    float* __restrict__ out, int n) {
    int hw = (blockIdx.x * blockDim.x + threadIdx.x) >> 4;  // half-warp per node
    int l  = threadIdx.x & 15;                               // 4-feature slice
    if (hw >= n) return;
    int node = hw;
    float d = g_dinv[node];
    float4 acc = ldrow4h(&g_bufAh[(size_t)node * 64 + l * 4]);
    float d2 = d * d;
    acc.x *= d2; acc.y *= d2; acc.z *= d2; acc.w *= d2;

    int s = g_off[node], e = g_off[node + 1];
    float2 ed;
    if (s < e) ed = __ldg(&g_edge[s]);
    for (int i = s; i < e; i++) {
        int src  = __float_as_int(ed.x);
        float w  = ed.y;
        if (i + 1 < e) ed = __ldg(&g_edge[i + 1]);
        float4 v = ldrow4h(&g_bufAh[(size_t)src * 64 + l * 4]);
        acc.x = fmaf(w, v.x, acc.x);
        acc.y = fmaf(w, v.y, acc.y);
        acc.z = fmaf(w, v.z, acc.z);
        acc.w = fmaf(w, v.w, acc.w);
    }

    // BN2 + ReLU + partial classifier for features c = l*4 .. l*4+3
    int c0 = l * 4;
    float a0 = 0.f, a1 = 0.f;
    float hv[4] = {acc.x, acc.y, acc.z, acc.w};
#pragma unroll
    for (int j = 0; j < 4; j++) {
        int c = c0 + j;
        float h = fmaxf(fmaf(hv[j], g_A[128 + c], g_Bc[128 + c]), 0.f);
        a0 = fmaf(h, __ldg(&cw[c * 2 + 0]), a0);
        a1 = fmaf(h, __ldg(&cw[c * 2 + 1]), a1);
    }
    // reduce across the 16 lanes of the half-warp (xor butterfly stays in-group)
#pragma unroll
    for (int o = 8; o >= 1; o >>= 1) {
        a0 += __shfl_xor_sync(0xffffffffu, a0, o);
        a1 += __shfl_xor_sync(0xffffffffu, a1, o);
    }
    if (l == 0) {
        out[(size_t)node * 2 + 0] = a0 + __ldg(&cb[0]);
        out[(size_t)node * 2 + 1] = a1 + __ldg(&cb[1]);
    }
}

// ---------------- Launch ----------------
extern "C" void kernel_launch(void* const* d_in, const int* in_sizes, int n_in,
                              void* d_out, int out_size) {
    const float* x      = (const float*)d_in[0];
    const int*   ei     = (const int*)d_in[1];     // int32 on the wire
    const float* w0     = (const float*)d_in[2];
    const float* w1     = (const float*)d_in[3];
    const float* w2     = (const float*)d_in[4];
    const float* biases = (const float*)d_in[5];
    const float* gamma  = (const float*)d_in[6];
    const float* beta   = (const float*)d_in[7];
    const float* rmean  = (const float*)d_in[8];
    const float* rvar   = (const float*)d_in[9];
    const float* clsw   = (const float*)d_in[10];
    const float* clsb   = (const float*)d_in[11];
    float* out = (float*)d_out;

    const int n = N_;
    const int nodeBlocks   = (n + 255) / 256;
    const int edgeBlocks   = (E_ + 255) / 256;
    const int scanBlocks   = (n + 1023) / 1024;      // 98
    const int gemmBlocks   = (n + 127) / 128;        // 782
    const int gatherBlocks = (n * 16 + 255) / 256;   // half-warp per node

    // launch index 3 (the ncu-profiled slot) = gemmt_k<128> — it only needs x,w0
    zero_bn_k<<<nodeBlocks, 256>>>(biases, gamma, beta, rmean, rvar);   // 0
    deg_k<<<edgeBlocks, 256>>>(ei);                                     // 1
    scan1_k<<<scanBlocks, 256>>>();                                     // 2 (+dinv)
    gemmt_k<128, false, true><<<gemmBlocks, 256>>>(x, w0, 0, n);        // 3 <- profiled
    scan2_k<<<1, 128>>>(scanBlocks);                                    // 4
    scan3_k<<<nodeBlocks, 256>>>();                                     // 5
    place_k<<<edgeBlocks, 256>>>(ei);                                   // 6

    // --- layer 0 aggregate ---
    gather_k<<<gatherBlocks, 256>>>(n);                                 // 7
    // --- layer 1 ---
    gemmt_k<64, true, false><<<gemmBlocks, 256>>>(nullptr, w1, 0, n);   // 8
    gather_k<<<gatherBlocks, 256>>>(n);                                 // 9
    // --- layer 2 ---
    gemmt_k<64, true, false><<<gemmBlocks, 256>>>(nullptr, w2, 64, n);  // 10
    gather_cls_k<<<gatherBlocks, 256>>>(clsw, clsb, out, n);            // 11 (fused)
}

// round 17
// speedup vs baseline: 1.3989x; 1.1868x over previous
#include <cuda_runtime.h>
#include <cuda_bf16.h>
#include <cuda_fp16.h>
#include <cstdint>

// ---------------- Problem constants (fixed shapes) ----------------
#define N_  100000
#define E_  1200000
#define IN_ 128
#define H_  64
#define OUT_ 2
#define EPS_ 1e-5f

// ---------------- Device scratch (no allocations allowed) ----------------
__device__ int    g_deg[N_];
__device__ float  g_dinv[N_];
__device__ int    g_off[N_ + 1];
__device__ int    g_part[128];
__device__ int    g_cursor[N_];
__device__ float2 g_edge[E_];                  // {src as int bits, norm}
__device__ __half g_bufAh[(size_t)N_ * H_];    // GEMM output t (fp16 rows, 128 B)
__device__ float  g_bufB[(size_t)N_ * H_];     // aggregated h (fp32)
__device__ float  g_A[3 * H_];                 // BN scale per layer/feature
__device__ float  g_Bc[3 * H_];                // BN shift (incl. bias)

// ---------------- tf32 helpers ----------------
__device__ __forceinline__ uint32_t tf32cvt(float f) {
    uint32_t u;
    asm("cvt.rna.tf32.f32 %0, %1;" : "=r"(u) : "f"(f));
    return u;
}
__device__ __forceinline__ void mma_tf32(float* c, uint32_t a0, uint32_t a1,
                                         uint32_t a2, uint32_t a3,
                                         uint32_t b0, uint32_t b1) {
    asm("mma.sync.aligned.m16n8k8.row.col.f32.tf32.tf32.f32 "
        "{%0,%1,%2,%3},{%4,%5,%6,%7},{%8,%9},{%0,%1,%2,%3};"
        : "+f"(c[0]), "+f"(c[1]), "+f"(c[2]), "+f"(c[3])
        : "r"(a0), "r"(a1), "r"(a2), "r"(a3), "r"(b0), "r"(b1));
}

// ---------------- Fused zero(deg) + BN-affine prep ----------------
__global__ void zero_bn_k(const float* __restrict__ biases, const float* __restrict__ gamma,
                          const float* __restrict__ beta, const float* __restrict__ mean,
                          const float* __restrict__ var) {
    int i = blockIdx.x * blockDim.x + threadIdx.x;
    if (i < N_) g_deg[i] = 0;
    if (i < 3 * H_) {
        float s = gamma[i] * rsqrtf(var[i] + EPS_);
        g_A[i]  = s;
        g_Bc[i] = (biases[i] - mean[i]) * s + beta[i];
    }
}

__global__ void deg_k(const int* __restrict__ ei) {
    int e = blockIdx.x * blockDim.x + threadIdx.x;
    if (e >= E_) return;
    int d = ei[E_ + e];                // col (target), int32 on the wire
    if ((unsigned)d < (unsigned)N_) atomicAdd(&g_deg[d], 1);
}

// ---------------- Exclusive scan over g_deg -> g_off (+dinv fused) ----------------
__global__ void scan1_k() {
    __shared__ int wsum[8];
    __shared__ int wpre[8];
    int tid  = threadIdx.x;
    int base = blockIdx.x * 1024 + tid * 4;
    int v[4]; int s = 0;
#pragma unroll
    for (int j = 0; j < 4; j++) {
        int i = base + j;
        v[j] = (i < N_) ? g_deg[i] : 0;
        if (i < N_) g_dinv[i] = rsqrtf((float)(v[j] + 1));   // +1 self loop
        s += v[j];
    }
    int lane = tid & 31, w = tid >> 5;
    int inc = s;
#pragma unroll
    for (int o = 1; o < 32; o <<= 1) {
        int t = __shfl_up_sync(0xffffffffu, inc, o);
        if (lane >= o) inc += t;
    }
    if (lane == 31) wsum[w] = inc;
    __syncthreads();
    if (tid == 0) {
        int r = 0;
#pragma unroll
        for (int k = 0; k < 8; k++) { wpre[k] = r; r += wsum[k]; }
        g_part[blockIdx.x] = r;
    }
    __syncthreads();
    int ex = wpre[w] + (inc - s);
#pragma unroll
    for (int j = 0; j < 4; j++) {
        int i = base + j;
        if (i < N_) g_off[i] = ex;
        ex += v[j];
    }
}

__global__ void scan2_k(int nb) {
    __shared__ int s[128];
    int t = threadIdx.x;
    int v = (t < nb) ? g_part[t] : 0;
    s[t] = v;
    __syncthreads();
#pragma unroll
    for (int o = 1; o < 128; o <<= 1) {
        int x = (t >= o) ? s[t - o] : 0;
        __syncthreads();
        s[t] += x;
        __syncthreads();
    }
    if (t < nb) g_part[t] = s[t] - v;   // exclusive
}

__global__ void scan3_k() {
    int i = blockIdx.x * blockDim.x + threadIdx.x;
    if (i < N_) {
        int o = g_off[i] + g_part[i >> 10];
        g_off[i]    = o;
        g_cursor[i] = o;
    }
    if (i == 0) g_off[N_] = E_;
}

// ---------------- CSR placement (counting sort by dst) ----------------
__global__ void place_k(const int* __restrict__ ei) {
    int e = blockIdx.x * blockDim.x + threadIdx.x;
    if (e >= E_) return;
    int s = ei[e];
    int d = ei[E_ + e];
    if ((unsigned)s >= (unsigned)N_ || (unsigned)d >= (unsigned)N_) return;
    float nm = g_dinv[s] * g_dinv[d];
    int p = atomicAdd(&g_cursor[d], 1);
    g_edge[p] = make_float2(__int_as_float(s), nm);
}

// ---------------- tf32 MMA GEMM: [n,K] @ [K,64] -> g_bufAh (fp16) ----------------
// Block: 128 nodes x 64 cols, 256 threads (8 warps, 3 CTAs/SM). Warp: 16 rows x 8 n-tiles.
// Vectorized staging: LDG.128 + STS.128 (strides 36/72 keep 4-k groups 16B-aligned).
#define KC_   32
#define XSTR_ 36
#define WSTR_ 72
template <int K, bool BN, bool EXT>
__global__ void __launch_bounds__(256, 3) gemmt_k(const float* __restrict__ Xext,
                                                  const float* __restrict__ W,
                                                  int abOff, int n) {
    __shared__ uint32_t Xs[128 * XSTR_];   // 18.4 KB
    __shared__ uint32_t Ws[KC_ * WSTR_];   //  9.2 KB
    const float* __restrict__ X = EXT ? Xext : g_bufB;
    int tid  = threadIdx.x;
    int lane = tid & 31, wid = tid >> 5;
    int gid  = lane >> 2, tgid = lane & 3;
    int node0 = blockIdx.x * 128;
    int wn0   = wid * 16;

    float acc[8][4];
#pragma unroll
    for (int t = 0; t < 8; t++)
#pragma unroll
        for (int j = 0; j < 4; j++) acc[t][j] = 0.f;

    for (int kc = 0; kc < K; kc += KC_) {
        // stage W chunk [32 k x 64 n]: 512 float4s, 2 per thread (LDG.128 -> STS.128)
#pragma unroll
        for (int m = 0; m < 2; m++) {
            int idx = tid + m * 256;
            int k = idx >> 4, j4 = (idx & 15) * 4;
            float4 v = *(const float4*)&W[(size_t)(kc + k) * 64 + j4];
            uint4 u = make_uint4(tf32cvt(v.x), tf32cvt(v.y), tf32cvt(v.z), tf32cvt(v.w));
            *(uint4*)&Ws[k * WSTR_ + j4] = u;
        }
        // stage X chunk [128 nodes x 32 k]: 1024 float4s, 4 per thread, fused BN+ReLU
#pragma unroll
        for (int m = 0; m < 4; m++) {
            int idx = tid + m * 256;
            int r = idx >> 3, c4 = (idx & 7) * 4;
            int node = node0 + r;
            float4 v = make_float4(0.f, 0.f, 0.f, 0.f);
            if (node < n) v = *(const float4*)&X[(size_t)node * K + kc + c4];
            if (BN) {
                int c0 = abOff + kc + c4;
                v.x = fmaxf(fmaf(v.x, g_A[c0 + 0], g_Bc[c0 + 0]), 0.f);
                v.y = fmaxf(fmaf(v.y, g_A[c0 + 1], g_Bc[c0 + 1]), 0.f);
                v.z = fmaxf(fmaf(v.z, g_A[c0 + 2], g_Bc[c0 + 2]), 0.f);
                v.w = fmaxf(fmaf(v.w, g_A[c0 + 3], g_Bc[c0 + 3]), 0.f);
            }
            uint4 u = make_uint4(tf32cvt(v.x), tf32cvt(v.y), tf32cvt(v.z), tf32cvt(v.w));
            *(uint4*)&Xs[r * XSTR_ + c4] = u;
        }
        __syncthreads();
#pragma unroll
        for (int k8 = 0; k8 < KC_; k8 += 8) {
            int r0 = wn0 + gid;
            uint32_t a0 = Xs[r0 * XSTR_ + k8 + tgid];
            uint32_t a1 = Xs[(r0 + 8) * XSTR_ + k8 + tgid];
            uint32_t a2 = Xs[r0 * XSTR_ + k8 + tgid + 4];
            uint32_t a3 = Xs[(r0 + 8) * XSTR_ + k8 + tgid + 4];
#pragma unroll
            for (int nt = 0; nt < 8; nt++) {
                uint32_t b0 = Ws[(k8 + tgid) * WSTR_ + nt * 8 + gid];
                uint32_t b1 = Ws[(k8 + tgid + 4) * WSTR_ + nt * 8 + gid];
                mma_tf32(acc[nt], a0, a1, a2, a3, b0, b1);
            }
        }
        __syncthreads();
    }
    // store fp16: per n-tile, rows (wn0+gid) and (+8), cols nt*8 + tgid*2 .. +1
    int nodeA = node0 + wn0 + gid;
    int nodeB = nodeA + 8;
#pragma unroll
    for (int nt = 0; nt < 8; nt++) {
        int col = nt * 8 + tgid * 2;
        if (nodeA < n)
            *(__half2*)&g_bufAh[(size_t)nodeA * 64 + col] = __floats2half2_rn(acc[nt][0], acc[nt][1]);
        if (nodeB < n)
            *(__half2*)&g_bufAh[(size_t)nodeB * 64 + col] = __floats2half2_rn(acc[nt][2], acc[nt][3]);
    }
}

// ---------------- fp16 row slice load helper: 4 features (8 B) -> float4 ----------------
__device__ __forceinline__ float4 ldrow4h(const __half* p) {
    uint2 u = *(const uint2*)p;
    __half2 ha = *(__half2*)&u.x, hb = *(__half2*)&u.y;
    float2 fa = __half22float2(ha), fb = __half22float2(hb);
    return make_float4(fa.x, fa.y, fb.x, fb.y);
}
__device__ __forceinline__ void fma4(float4& acc, float w, const float4& v) {
    acc.x = fmaf(w, v.x, acc.x);
    acc.y = fmaf(w, v.y, acc.y);
    acc.z = fmaf(w, v.z, acc.z);
    acc.w = fmaf(w, v.w, acc.w);
}

// ---------------- Pull aggregation: MLP-4 unroll, fp16 reads, fp32 accumulate ----------------
__global__ void __launch_bounds__(256) gather_k(int n) {
    int hw = (blockIdx.x * blockDim.x + threadIdx.x) >> 4;  // half-warp per node
    int l  = threadIdx.x & 15;                               // 4-feature slice of the row
    if (hw >= n) return;
    int node = hw;
    float d = g_dinv[node];
    float4 acc = ldrow4h(&g_bufAh[(size_t)node * 64 + l * 4]);
    float d2 = d * d;
    acc.x *= d2; acc.y *= d2; acc.z *= d2; acc.w *= d2;

    int s = g_off[node], e = g_off[node + 1];
    int i = s;
    for (; i + 4 <= e; i += 4) {
        float2 e0 = __ldg(&g_edge[i]);
        float2 e1 = __ldg(&g_edge[i + 1]);
        float2 e2 = __ldg(&g_edge[i + 2]);
        float2 e3 = __ldg(&g_edge[i + 3]);
        float4 v0 = ldrow4h(&g_bufAh[(size_t)__float_as_int(e0.x) * 64 + l * 4]);
        float4 v1 = ldrow4h(&g_bufAh[(size_t)__float_as_int(e1.x) * 64 + l * 4]);
        float4 v2 = ldrow4h(&g_bufAh[(size_t)__float_as_int(e2.x) * 64 + l * 4]);
        float4 v3 = ldrow4h(&g_bufAh[(size_t)__float_as_int(e3.x) * 64 + l * 4]);
        fma4(acc, e0.y, v0); fma4(acc, e1.y, v1);
        fma4(acc, e2.y, v2); fma4(acc, e3.y, v3);
    }
    if (i + 2 <= e) {
        float2 e0 = __ldg(&g_edge[i]);
        float2 e1 = __ldg(&g_edge[i + 1]);
        float4 v0 = ldrow4h(&g_bufAh[(size_t)__float_as_int(e0.x) * 64 + l * 4]);
        float4 v1 = ldrow4h(&g_bufAh[(size_t)__float_as_int(e1.x) * 64 + l * 4]);
        fma4(acc, e0.y, v0); fma4(acc, e1.y, v1);
        i += 2;
    }
    if (i < e) {
        float2 e0 = __ldg(&g_edge[i]);
        float4 v0 = ldrow4h(&g_bufAh[(size_t)__float_as_int(e0.x) * 64 + l * 4]);
        fma4(acc, e0.y, v0);
    }
    *(float4*)&g_bufB[(size_t)node * 64 + l * 4] = acc;
}

// ---------------- Fused gather3 + BN2 + ReLU + classifier (MLP-4) ----------------
__global__ void __launch_bounds__(256) gather_cls_k(const float* __restrict__ cw,
                                                    const float* __restrict__ cb,
                                                    float* __restrict__ out, int n) {
    int hw = (blockIdx.x * blockDim.x + threadIdx.x) >> 4;  // half-warp per node
    int l  = threadIdx.x & 15;                               // 4-feature slice
    if (hw >= n) return;
    int node = hw;
    float d = g_dinv[node];
    float4 acc = ldrow4h(&g_bufAh[(size_t)node * 64 + l * 4]);
    float d2 = d * d;
    acc.x *= d2; acc.y *= d2; acc.z *= d2; acc.w *= d2;

    int s = g_off[node], e = g_off[node + 1];
    int i = s;
    for (; i + 4 <= e; i += 4) {
        float2 e0 = __ldg(&g_edge[i]);
        float2 e1 = __ldg(&g_edge[i + 1]);
        float2 e2 = __ldg(&g_edge[i + 2]);
        float2 e3 = __ldg(&g_edge[i + 3]);
        float4 v0 = ldrow4h(&g_bufAh[(size_t)__float_as_int(e0.x) * 64 + l * 4]);
        float4 v1 = ldrow4h(&g_bufAh[(size_t)__float_as_int(e1.x) * 64 + l * 4]);
        float4 v2 = ldrow4h(&g_bufAh[(size_t)__float_as_int(e2.x) * 64 + l * 4]);
        float4 v3 = ldrow4h(&g_bufAh[(size_t)__float_as_int(e3.x) * 64 + l * 4]);
        fma4(acc, e0.y, v0); fma4(acc, e1.y, v1);
        fma4(acc, e2.y, v2); fma4(acc, e3.y, v3);
    }
    if (i + 2 <= e) {
        float2 e0 = __ldg(&g_edge[i]);
        float2 e1 = __ldg(&g_edge[i + 1]);
        float4 v0 = ldrow4h(&g_bufAh[(size_t)__float_as_int(e0.x) * 64 + l * 4]);
        float4 v1 = ldrow4h(&g_bufAh[(size_t)__float_as_int(e1.x) * 64 + l * 4]);
        fma4(acc, e0.y, v0); fma4(acc, e1.y, v1);
        i += 2;
    }
    if (i < e) {
        float2 e0 = __ldg(&g_edge[i]);
        float4 v0 = ldrow4h(&g_bufAh[(size_t)__float_as_int(e0.x) * 64 + l * 4]);
        fma4(acc, e0.y, v0);
    }

    // BN2 + ReLU + partial classifier for features c = l*4 .. l*4+3
    int c0 = l * 4;
    float a0 = 0.f, a1 = 0.f;
    float hv[4] = {acc.x, acc.y, acc.z, acc.w};
#pragma unroll
    for (int j = 0; j < 4; j++) {
        int c = c0 + j;
        float h = fmaxf(fmaf(hv[j], g_A[128 + c], g_Bc[128 + c]), 0.f);
        a0 = fmaf(h, __ldg(&cw[c * 2 + 0]), a0);
        a1 = fmaf(h, __ldg(&cw[c * 2 + 1]), a1);
    }
    // reduce across the 16 lanes of the half-warp (xor butterfly stays in-group)
#pragma unroll
    for (int o = 8; o >= 1; o >>= 1) {
        a0 += __shfl_xor_sync(0xffffffffu, a0, o);
        a1 += __shfl_xor_sync(0xffffffffu, a1, o);
    }
    if (l == 0) {
        out[(size_t)node * 2 + 0] = a0 + __ldg(&cb[0]);
        out[(size_t)node * 2 + 1] = a1 + __ldg(&cb[1]);
    }
}

// ---------------- Launch ----------------
extern "C" void kernel_launch(void* const* d_in, const int* in_sizes, int n_in,
                              void* d_out, int out_size) {
    const float* x      = (const float*)d_in[0];
    const int*   ei     = (const int*)d_in[1];     // int32 on the wire
    const float* w0     = (const float*)d_in[2];
    const float* w1     = (const float*)d_in[3];
    const float* w2     = (const float*)d_in[4];
    const float* biases = (const float*)d_in[5];
    const float* gamma  = (const float*)d_in[6];
    const float* beta   = (const float*)d_in[7];
    const float* rmean  = (const float*)d_in[8];
    const float* rvar   = (const float*)d_in[9];
    const float* clsw   = (const float*)d_in[10];
    const float* clsb   = (const float*)d_in[11];
    float* out = (float*)d_out;

    const int n = N_;
    const int nodeBlocks   = (n + 255) / 256;
    const int edgeBlocks   = (E_ + 255) / 256;
    const int scanBlocks   = (n + 1023) / 1024;      // 98
    const int gemmBlocks   = (n + 127) / 128;        // 782
    const int gatherBlocks = (n * 16 + 255) / 256;   // half-warp per node

    // launch index 3 (the ncu-profiled slot) = gemmt_k<128> — it only needs x,w0
    zero_bn_k<<<nodeBlocks, 256>>>(biases, gamma, beta, rmean, rvar);   // 0
    deg_k<<<edgeBlocks, 256>>>(ei);                                     // 1
    scan1_k<<<scanBlocks, 256>>>();                                     // 2 (+dinv)
    gemmt_k<128, false, true><<<gemmBlocks, 256>>>(x, w0, 0, n);        // 3 <- profiled
    scan2_k<<<1, 128>>>(scanBlocks);                                    // 4
    scan3_k<<<nodeBlocks, 256>>>();                                     // 5
    place_k<<<edgeBlocks, 256>>>(ei);                                   // 6

    // --- layer 0 aggregate ---
    gather_k<<<gatherBlocks, 256>>>(n);                                 // 7
    // --- layer 1 ---
    gemmt_k<64, true, false><<<gemmBlocks, 256>>>(nullptr, w1, 0, n);   // 8
    gather_k<<<gatherBlocks, 256>>>(n);                                 // 9
    // --- layer 2 ---
    gemmt_k<64, true, false><<<gemmBlocks, 256>>>(nullptr, w2, 64, n);  // 10
    gather_cls_k<<<gatherBlocks, 256>>>(clsw, clsb, out, n);            // 11 (fused)
}